// round 11
// baseline (speedup 1.0000x reference)
#include <cuda_runtime.h>
#include <cuda_bf16.h>
#include <cstdint>

// Problem: B=256, N=64, d=64. Outputs concatenated: alphas [B,N,N,1] then value [B,N,N,64].
constexpr int Bn = 256;
constexpr int Nn = 64;
constexpr int Dn = 64;
constexpr float NEG_SLOPE = 0.01f;

// dynamic smem layout (bytes)
constexpr int OFF_WB  = 0;                       // 64 f32
constexpr int OFF_AW  = 256;                     // 64 f32
constexpr int OFF_LOG = 512;                     // 512 f32 (8 i's x 64 logits) = 2048
constexpr int OFF_XI  = 2560;                    // 8 i-rows natural fp32, stride 72: 2304
constexpr int OFF_SF  = 4992;                    // E frag table fp32 (swizzled): 16384
constexpr int OFF_SB  = OFF_SF + 16384;          // W frag table bf16 hi/lo (swizzled): 16384
constexpr int SMEM_TOTAL = OFF_SB + 16384;       // 37760 B

static __device__ __forceinline__ void mma_bf16(float* c, const uint32_t* a, const uint32_t* b) {
    asm volatile(
        "mma.sync.aligned.m16n8k16.row.col.f32.bf16.bf16.f32 "
        "{%0,%1,%2,%3}, {%4,%5,%6,%7}, {%8,%9}, {%0,%1,%2,%3};"
        : "+f"(c[0]), "+f"(c[1]), "+f"(c[2]), "+f"(c[3])
        : "r"(a[0]), "r"(a[1]), "r"(a[2]), "r"(a[3]), "r"(b[0]), "r"(b[1]));
}

// split fp32 pair -> packed bf16x2 hi and bf16x2 lo (lo via bit-extracted hi)
static __device__ __forceinline__ void split2(float a, float b, uint32_t& hi, uint32_t& lo) {
    __nv_bfloat162 h = __floats2bfloat162_rn(a, b);
    uint32_t hu = *reinterpret_cast<uint32_t*>(&h);
    float hax = __uint_as_float(hu << 16);
    float hay = __uint_as_float(hu & 0xFFFF0000u);
    __nv_bfloat162 l = __floats2bfloat162_rn(a - hax, b - hay);
    hi = hu;
    lo = *reinterpret_cast<uint32_t*>(&l);
}

static __device__ __forceinline__ void stcs4(float* p, float4 v) {
    asm volatile("st.global.cs.v4.f32 [%0], {%1,%2,%3,%4};"
                 :: "l"(p), "f"(v.x), "f"(v.y), "f"(v.z), "f"(v.w) : "memory");
}

// swizzled byte offset of 16B unit (j*4+q) inside ks-block of a frag table.
static __device__ __forceinline__ uint32_t swzoff(int j, int q, int ks) {
    uint32_t u = (uint32_t)(j * 4 + q);
    uint32_t t = (((uint32_t)j & 3u) << 1) | (((uint32_t)ks >> 1) & 1u);
    return ((uint32_t)ks << 12) + ((u ^ t) << 4);
}

// One CTA: (b, i0..i7 = 8*ib..8*ib+7), 256 threads / 8 warps.
// Shared E fp32 frag table + W bf16 frag table filled once.
// 4 GEMM passes; pass p: warps 0-3 -> i(2p) (16 j-rows each), warps 4-7 -> i(2p+1).
// M=16/warp (32-reg acc); <=64 regs -> 4 CTAs/SM, 32 warps.
__global__ __launch_bounds__(256, 4)
void afm_mma(const float* __restrict__ emb,
             const float* __restrict__ wW,
             const float* __restrict__ wb,
             const float* __restrict__ aW,
             float* __restrict__ outA,
             float* __restrict__ outV)
{
    extern __shared__ __align__(16) char smem[];
    const int ib  = blockIdx.x;   // 0..7
    const int b   = blockIdx.y;   // 0..255
    const int tx  = threadIdx.x;
    const int wid = tx >> 5;      // 0..7
    const int lid = tx & 31;
    const int g   = lid >> 2;     // 0..7
    const int q   = lid & 3;      // 0..3

    float* sWB  = reinterpret_cast<float*>(smem + OFF_WB);
    float* sAW  = reinterpret_cast<float*>(smem + OFF_AW);
    float* sLOG = reinterpret_cast<float*>(smem + OFF_LOG);
    float* sXI  = reinterpret_cast<float*>(smem + OFF_XI);

    const int jr = tx >> 2;       // row 0..63 this thread fills
    const int qt = tx & 3;        // 16-float quarter of the row (= ks block)

    const float* embB = emb + (size_t)b * Nn * Dn;

    if (tx < 64) { sWB[tx] = wb[tx]; sAW[tx] = aW[tx]; }
    // natural-order copy of the CTA's 8 i-rows (8 rows x 16 float4 = 128 float4)
    if (tx < 128) {
        const int row = tx >> 4;   // 0..7
        const int c4  = tx & 15;
        reinterpret_cast<float4*>(sXI + row * 72)[c4] =
            reinterpret_cast<const float4*>(embB + (8 * ib + row) * Dn)[c4];
    }

    // ---- phase 1: E quarter-row -> ereg + sF (swizzled fp32 frag table) ----
    {
        float4 ereg[4];
        const float4* src = reinterpret_cast<const float4*>(embB + jr * Dn + qt * 16);
        #pragma unroll
        for (int k = 0; k < 4; k++) ereg[k] = src[k];
        #pragma unroll
        for (int qq = 0; qq < 4; qq++) {
            float4 va = ereg[qq >> 1];
            float4 vb = ereg[2 + (qq >> 1)];
            float ax = (qq & 1) ? va.z : va.x;
            float ay = (qq & 1) ? va.w : va.y;
            float bx = (qq & 1) ? vb.z : vb.x;
            float by = (qq & 1) ? vb.w : vb.y;
            *reinterpret_cast<float4*>(smem + OFF_SF + swzoff(jr, qq, qt)) =
                make_float4(ax, ay, bx, by);
        }
        __syncthreads();   // sXI visible for value writes

        // ---- phase 2: value writes (ereg dies here, before W split regs) ----
        #pragma unroll
        for (int L = 0; L < 8; L++) {
            const int iGlob = 8 * ib + L;
            const float4* xi = reinterpret_cast<const float4*>(sXI + L * 72 + qt * 16);
            float* oV = outV + ((((size_t)b * Nn + iGlob) * Nn + jr) * Dn + qt * 16);
            #pragma unroll
            for (int k = 0; k < 4; k++) {
                float4 x4 = xi[k];
                float4 e4 = ereg[k];
                stcs4(oV + 4 * k, make_float4(e4.x * x4.x, e4.y * x4.y, e4.z * x4.z, e4.w * x4.w));
            }
        }
    }

    // ---- phase 3: W quarter-row -> bf16 hi/lo splits -> sB frag table ----
    {
        const float4* src = reinterpret_cast<const float4*>(wW + jr * Dn + qt * 16);
        uint32_t hu[8], lu[8];
        #pragma unroll
        for (int k = 0; k < 4; k++) {
            float4 w4 = src[k];
            split2(w4.x, w4.y, hu[2 * k],     lu[2 * k]);
            split2(w4.z, w4.w, hu[2 * k + 1], lu[2 * k + 1]);
        }
        #pragma unroll
        for (int qq = 0; qq < 4; qq++) {
            *reinterpret_cast<uint4*>(smem + OFF_SB + swzoff(jr, qq, qt)) =
                make_uint4(hu[qq], hu[qq + 4], lu[qq], lu[qq + 4]);
        }
    }
    __syncthreads();

    // ---- GEMM passes: per i, D[64x64] = (E*x_i) @ W^T, 3-term bf16 emulation ----
    const int jw = (wid & 3) * 16;                 // this warp's 16 j-rows

    #pragma unroll
    for (int p = 0; p < 4; p++) {
        const int iLocal = 2 * p + (wid >> 2);     // this warp's i (0..7)
        const float* sXiN = sXI + iLocal * 72;

        float acc[8][4];
        #pragma unroll
        for (int nt = 0; nt < 8; nt++)
            #pragma unroll
            for (int r = 0; r < 4; r++) acc[nt][r] = 0.0f;

        #pragma unroll
        for (int ks = 0; ks < 4; ks++) {
            const int kc = ks * 16 + 2 * q;
            const float2 xa = *reinterpret_cast<const float2*>(sXiN + kc);
            const float2 xb = *reinterpret_cast<const float2*>(sXiN + kc + 8);

            uint32_t ah[4], al[4];
            {
                const float4 f0 = *reinterpret_cast<const float4*>(
                    smem + OFF_SF + swzoff(jw + g, q, ks));
                const float4 f1 = *reinterpret_cast<const float4*>(
                    smem + OFF_SF + swzoff(jw + g + 8, q, ks));
                split2(f0.x * xa.x, f0.y * xa.y, ah[0], al[0]);
                split2(f1.x * xa.x, f1.y * xa.y, ah[1], al[1]);
                split2(f0.z * xb.x, f0.w * xb.y, ah[2], al[2]);
                split2(f1.z * xb.x, f1.w * xb.y, ah[3], al[3]);
            }
            #pragma unroll
            for (int nt = 0; nt < 8; nt++) {
                const uint4 bv = *reinterpret_cast<const uint4*>(
                    smem + OFF_SB + swzoff(nt * 8 + g, q, ks));
                uint32_t bh[2] = {bv.x, bv.y};
                uint32_t bl[2] = {bv.z, bv.w};
                mma_bf16(acc[nt], ah, bh);
                mma_bf16(acc[nt], ah, bl);
                mma_bf16(acc[nt], al, bh);
            }
        }

        // ---- epilogue: bias + LeakyReLU + dot(aW) -> logits for this pass ----
        #pragma unroll
        for (int half = 0; half < 2; half++) {
            float pl = 0.0f;
            #pragma unroll
            for (int nt = 0; nt < 8; nt++) {
                const int e0 = nt * 8 + 2 * q;
                float q0 = acc[nt][half * 2 + 0] + sWB[e0];
                float q1 = acc[nt][half * 2 + 1] + sWB[e0 + 1];
                q0 = (q0 >= 0.0f) ? q0 : NEG_SLOPE * q0;
                q1 = (q1 >= 0.0f) ? q1 : NEG_SLOPE * q1;
                pl = fmaf(sAW[e0], q0, pl);
                pl = fmaf(sAW[e0 + 1], q1, pl);
            }
            pl += __shfl_xor_sync(0xffffffffu, pl, 1);
            pl += __shfl_xor_sync(0xffffffffu, pl, 2);
            if (q == 0) sLOG[iLocal * 64 + jw + half * 8 + g] = pl;  // disjoint per pass
        }
    }
    __syncthreads();

    // ---- softmax per i over 64 j's: warp w -> i = w ----
    {
        const int iL = wid;
        float v0 = sLOG[iL * 64 + lid];
        float v1 = sLOG[iL * 64 + lid + 32];
        float m = fmaxf(v0, v1);
        #pragma unroll
        for (int msk = 16; msk >= 1; msk >>= 1)
            m = fmaxf(m, __shfl_xor_sync(0xffffffffu, m, msk));
        float e0 = __expf(v0 - m);
        float e1 = __expf(v1 - m);
        float s = e0 + e1;
        #pragma unroll
        for (int msk = 16; msk >= 1; msk >>= 1)
            s += __shfl_xor_sync(0xffffffffu, s, msk);
        const float inv = 1.0f / s;
        const int iGlob = 8 * ib + iL;
        float* oa = outA + ((size_t)b * Nn + iGlob) * Nn;
        oa[lid]      = e0 * inv;
        oa[lid + 32] = e1 * inv;
    }
}

extern "C" void kernel_launch(void* const* d_in, const int* in_sizes, int n_in,
                              void* d_out, int out_size)
{
    (void)in_sizes; (void)n_in; (void)out_size;
    const float* emb = (const float*)d_in[0];
    const float* wW  = (const float*)d_in[1];
    const float* wb  = (const float*)d_in[2];
    const float* aW  = (const float*)d_in[3];
    // d_in[4] = a_b: constant shift, cancels in softmax

    float* out  = (float*)d_out;
    float* outA = out;
    float* outV = out + (size_t)Bn * Nn * Nn;

    cudaFuncSetAttribute(afm_mma, cudaFuncAttributeMaxDynamicSharedMemorySize, SMEM_TOTAL);
    dim3 grid(Nn / 8, Bn);
    afm_mma<<<grid, 256, SMEM_TOTAL>>>(emb, wW, wb, aW, outA, outV);
}